// round 17
// baseline (speedup 1.0000x reference)
#include <cuda_runtime.h>
#include <cuda_fp16.h>
#include <cstdint>

// Problem dims
#define Bb 16384
#define Hh 1024
#define Nn 4096   // 4*H
#define Kk 2048   // D + H

// GEMM tiling: CTA 128x128x32(halves), 8 warps, warp tile 64x32, occ 2
#define BM 128
#define BN 128
#define BK 32               // halves per k-stage (64B rows)
#define KT (Kk / BK)        // 64
#define STAGES 4
#define A_BYTES (BM * BK * 2)            // 8192
#define B_BYTES (BN * BK * 2)            // 8192
#define STAGE_BYTES (A_BYTES + B_BYTES)  // 16384
#define A_WORDS (A_BYTES / 4)            // 2048
#define GEMM_SMEM_BYTES (STAGES * STAGE_BYTES)   // 65536 = 64KB

// Scratch (device globals — allocation-free per harness rules)
__device__ __half g_Ah[(size_t)Bb * Kk];    // [x | h], fp16, K-major (64MB)
__device__ __half g_Wh[(size_t)Nn * Kk];    // [Wi | Wh], fp16, K-major (16MB)
__device__ __half g_preh[(size_t)Bb * Nn];  // pre-activations fp16 (128MB)

// ---------------------------------------------------------------------------
// fp16 pack/unpack helpers (inline PTX; header-version-proof)
// ---------------------------------------------------------------------------
__device__ __forceinline__ uint32_t f16x2(float lo, float hi) {
    uint32_t u;
    asm("cvt.rn.f16x2.f32 %0, %1, %2;" : "=r"(u) : "f"(hi), "f"(lo));
    return u;
}
__device__ __forceinline__ float2 h2f(uint32_t u) {
    float lo, hi;
    asm("{ .reg .f16 l, h; mov.b32 {l, h}, %2;"
        "  cvt.f32.f16 %0, l; cvt.f32.f16 %1, h; }"
        : "=f"(lo), "=f"(hi) : "r"(u));
    return make_float2(lo, hi);
}
__device__ __forceinline__ uint4 pack8(float4 v0, float4 v1) {
    uint4 o;
    o.x = f16x2(v0.x, v0.y);
    o.y = f16x2(v0.z, v0.w);
    o.z = f16x2(v1.x, v1.y);
    o.w = f16x2(v1.z, v1.w);
    return o;
}

// ---------------------------------------------------------------------------
// Pack kernels: concatenate along K and convert fp32 -> fp16 (RN).
// ---------------------------------------------------------------------------
__global__ void pack_A(const float* __restrict__ x, const float* __restrict__ h) {
    size_t i = (size_t)blockIdx.x * blockDim.x + threadIdx.x;  // 8-float group
    size_t b = i >> 8;
    int g8 = (int)(i & 255);
    const float4* src = (g8 < 128)
        ? reinterpret_cast<const float4*>(x + b * 1024) + g8 * 2
        : reinterpret_cast<const float4*>(h + b * 1024) + (g8 - 128) * 2;
    reinterpret_cast<uint4*>(g_Ah)[i] = pack8(src[0], src[1]);
}
__global__ void pack_W(const float* __restrict__ Wi, const float* __restrict__ Wh) {
    size_t i = (size_t)blockIdx.x * blockDim.x + threadIdx.x;
    size_t n = i >> 8;
    int g8 = (int)(i & 255);
    const float4* src = (g8 < 128)
        ? reinterpret_cast<const float4*>(Wi + n * 1024) + g8 * 2
        : reinterpret_cast<const float4*>(Wh + n * 1024) + (g8 - 128) * 2;
    reinterpret_cast<uint4*>(g_Wh)[i] = pack8(src[0], src[1]);
}

// ---------------------------------------------------------------------------
// FP16 mma.sync GEMM (m16n8k16): g_preh = g_Ah (16384x2048) * g_Wh^T
// ---------------------------------------------------------------------------
// 16B-chunk XOR swizzle (64B rows): chunk c -> c ^ ((r>>1)&3); word form below.
__device__ __forceinline__ int swzw(int r, int w) {
    return r * 16 + ((((w >> 2) ^ ((r >> 1) & 3))) << 2) + (w & 3);
}
__device__ __forceinline__ void cp16(uint32_t s, const void* g) {
    asm volatile("cp.async.cg.shared.global [%0], [%1], 16;" :: "r"(s), "l"(g));
}
__device__ __forceinline__ void cp_commit() { asm volatile("cp.async.commit_group;"); }
template <int N>
__device__ __forceinline__ void cp_wait() { asm volatile("cp.async.wait_group %0;" :: "n"(N)); }

__global__ void __launch_bounds__(256, 2) gemm_f16() {
    extern __shared__ char smem[];
    uint32_t smem_u;
    asm("{ .reg .u64 t; cvta.to.shared.u64 t, %1; cvt.u32.u64 %0, t; }"
        : "=r"(smem_u) : "l"(smem));

    // Band schedule: ntile inner -> wave shares A band; W (16MB) L2-resident.
    int bid = blockIdx.x;
    int ntile = bid & 31;     // 32 n-tiles of 128
    int mtile = bid >> 5;     // 128 m-tiles of 128

    int tid = threadIdx.x;
    int lane = tid & 31, warp = tid >> 5;
    int wm = warp & 1, wn = warp >> 1;    // 2 x 4 warp grid, warp tile 64x32
    int rq = lane >> 2, cq = lane & 3;

    const __half* gA = g_Ah + (size_t)mtile * BM * Kk;
    const __half* gB = g_Wh + (size_t)ntile * BN * Kk;

    float acc[4][4][4];
#pragma unroll
    for (int i = 0; i < 4; i++)
#pragma unroll
        for (int j = 0; j < 4; j++)
#pragma unroll
            for (int l = 0; l < 4; l++) acc[i][j][l] = 0.f;

    auto load_stage = [&](int s, int kt) {
        uint32_t as = smem_u + (uint32_t)(s * STAGE_BYTES);
        uint32_t bs = as + A_BYTES;
        // A: 512 16B chunks (128 rows x 4), B: same
#pragma unroll
        for (int i = 0; i < 2; i++) {
            int ch = i * 256 + tid;
            int row = ch >> 2, c = ch & 3;
            uint32_t cs = (uint32_t)(c ^ ((row >> 1) & 3));
            cp16(as + (uint32_t)row * 64 + cs * 16,
                 gA + (size_t)row * Kk + kt * BK + c * 8);
        }
#pragma unroll
        for (int i = 0; i < 2; i++) {
            int ch = i * 256 + tid;
            int row = ch >> 2, c = ch & 3;
            uint32_t cs = (uint32_t)(c ^ ((row >> 1) & 3));
            cp16(bs + (uint32_t)row * 64 + cs * 16,
                 gB + (size_t)row * Kk + kt * BK + c * 8);
        }
    };

#pragma unroll
    for (int s = 0; s < STAGES - 1; s++) { load_stage(s, s); cp_commit(); }

    for (int kt = 0; kt < KT; kt++) {
        cp_wait<STAGES - 2>();
        __syncthreads();

        int pf = kt + STAGES - 1;
        if (pf < KT) load_stage(pf & (STAGES - 1), pf);
        cp_commit();

        const uint32_t* as =
            reinterpret_cast<const uint32_t*>(smem + (kt & (STAGES - 1)) * STAGE_BYTES);
        const uint32_t* bs = as + A_WORDS;

#pragma unroll
        for (int k16 = 0; k16 < 2; k16++) {
            int w0 = k16 * 8 + cq;
            int w1 = w0 + 4;
            uint32_t a[4][4], b[4][2];
#pragma unroll
            for (int mi = 0; mi < 4; mi++) {
                int r = wm * 64 + mi * 16 + rq;
                a[mi][0] = as[swzw(r,     w0)];
                a[mi][1] = as[swzw(r + 8, w0)];
                a[mi][2] = as[swzw(r,     w1)];
                a[mi][3] = as[swzw(r + 8, w1)];
            }
#pragma unroll
            for (int ni = 0; ni < 4; ni++) {
                int rn = wn * 32 + ni * 8 + rq;
                b[ni][0] = bs[swzw(rn, w0)];
                b[ni][1] = bs[swzw(rn, w1)];
            }
#pragma unroll
            for (int mi = 0; mi < 4; mi++)
#pragma unroll
                for (int ni = 0; ni < 4; ni++) {
                    float* c = acc[mi][ni];
                    asm volatile(
                        "mma.sync.aligned.m16n8k16.row.col.f32.f16.f16.f32 "
                        "{%0,%1,%2,%3}, {%4,%5,%6,%7}, {%8,%9}, {%0,%1,%2,%3};"
                        : "+f"(c[0]), "+f"(c[1]), "+f"(c[2]), "+f"(c[3])
                        : "r"(a[mi][0]), "r"(a[mi][1]), "r"(a[mi][2]), "r"(a[mi][3]),
                          "r"(b[ni][0]), "r"(b[ni][1]));
                }
        }
    }

    // Epilogue: store fp16 pre-activations (4B half2 stores)
    size_t baseM = (size_t)mtile * BM + wm * 64;
    size_t baseN = (size_t)ntile * BN + wn * 32;
#pragma unroll
    for (int mi = 0; mi < 4; mi++)
#pragma unroll
        for (int ni = 0; ni < 4; ni++) {
            size_t r = baseM + mi * 16 + rq;
            size_t cc = baseN + ni * 8 + cq * 2;
            *reinterpret_cast<uint32_t*>(g_preh + r * Nn + cc) =
                f16x2(acc[mi][ni][0], acc[mi][ni][1]);
            *reinterpret_cast<uint32_t*>(g_preh + (r + 8) * Nn + cc) =
                f16x2(acc[mi][ni][2], acc[mi][ni][3]);
        }
}

// ---------------------------------------------------------------------------
// Elementwise LSTM gate update: reads fp16 pre, fp32 everything else.
// ---------------------------------------------------------------------------
__device__ __forceinline__ float sigm(float x) { return 1.f / (1.f + __expf(-x)); }
__device__ __forceinline__ float tanh_f(float x) { return 2.f * sigm(2.f * x) - 1.f; }

__global__ void lstm_elem(const float* __restrict__ c, const float* __restrict__ bi,
                          float* __restrict__ out, int out_size) {
    int i4 = blockIdx.x * blockDim.x + threadIdx.x;  // group of 4 h
    int b = i4 >> 8, h4 = i4 & 255;
    const uint2* p = reinterpret_cast<const uint2*>(g_preh + (size_t)b * Nn);
    const float4* b4 = reinterpret_cast<const float4*>(bi);

    uint2 ui = p[h4];
    uint2 uf = p[256 + h4];
    uint2 ug = p[512 + h4];
    uint2 uo = p[768 + h4];
    float2 i01 = h2f(ui.x), i23 = h2f(ui.y);
    float2 f01 = h2f(uf.x), f23 = h2f(uf.y);
    float2 g01 = h2f(ug.x), g23 = h2f(ug.y);
    float2 o01 = h2f(uo.x), o23 = h2f(uo.y);
    float4 pi = make_float4(i01.x, i01.y, i23.x, i23.y);
    float4 pf = make_float4(f01.x, f01.y, f23.x, f23.y);
    float4 pg = make_float4(g01.x, g01.y, g23.x, g23.y);
    float4 po = make_float4(o01.x, o01.y, o23.x, o23.y);

    float4 vb0 = b4[h4], vb1 = b4[256 + h4], vb2 = b4[512 + h4], vb3 = b4[768 + h4];
    float4 cv = reinterpret_cast<const float4*>(c)[i4];

    float4 go, nh, nc;
    {
        float gi, gf, gg, gO, t;
#define LANE(W)                                                         \
        gi = sigm(pi.W + vb0.W); gf = sigm(pf.W + vb1.W);               \
        gg = tanh_f(pg.W + vb2.W); gO = sigm(po.W + vb3.W);             \
        nc.W = gf * cv.W + gi * gg; t = tanh_f(nc.W);                   \
        nh.W = gO * t; go.W = gO;
        LANE(x) LANE(y) LANE(z) LANE(w)
#undef LANE
    }

    float4* o4 = reinterpret_cast<float4*>(out);
    o4[i4] = go;
    if (out_size >= 3 * Bb * Hh) {
        o4[(Bb * Hh / 4) + i4]     = nh;
        o4[(2 * Bb * Hh / 4) + i4] = nc;
    }
}

// ---------------------------------------------------------------------------
// Launch: pack -> GEMM -> elementwise (graph-capturable)
// ---------------------------------------------------------------------------
extern "C" void kernel_launch(void* const* d_in, const int* in_sizes, int n_in,
                              void* d_out, int out_size) {
    const float* x  = (const float*)d_in[0];
    const float* h  = (const float*)d_in[1];
    const float* c  = (const float*)d_in[2];
    const float* Wi = (const float*)d_in[3];
    const float* bi = (const float*)d_in[4];
    const float* Wh = (const float*)d_in[5];
    float* out = (float*)d_out;

    pack_A<<<16384, 256>>>(x, h);     // B*K/8 groups
    pack_W<<<4096, 256>>>(Wi, Wh);    // N*K/8 groups

    cudaFuncSetAttribute(gemm_f16, cudaFuncAttributeMaxDynamicSharedMemorySize,
                         GEMM_SMEM_BYTES);
    gemm_f16<<<(Bb / BM) * (Nn / BN), 256, GEMM_SMEM_BYTES>>>();  // 4096 CTAs

    lstm_elem<<<(Bb * Hh / 4) / 256, 256>>>(c, bi, out, out_size);
}